// round 3
// baseline (speedup 1.0000x reference)
#include <cuda_runtime.h>
#include <cstdint>

// EngramMemory: hashed n-gram embedding gather.
// tokens: (4, 4096) int64 or int32 (dtype auto-detected at runtime)
// tables: (8, 2048, 256) f32   (orders {2,3} x 4 heads)
// out:    (4, 4096, 2048) f32
//
// For order index oi (order = 2+oi), head hd:
//   seed = 1337 + 97*order + 17*hd
//   hash = 0; for i in 0..order-1 (oldest->newest token in window, zero-padded):
//       hash = (hash*1000003 + tok + seed) mod 2048
//   out[b,s, oi*1024 + hd*256 : +256] = tables[oi*4+hd][hash]
//
// mod 2048 is a power of two => exact in uint32:
// h <= 2047, 2047*1000003 + 50256 + seed < 2^31, so uint32 arithmetic is exact.

#define B_      4
#define S_      4096
#define NHEADS  4
#define NBUCK   2048u
#define HD      256
#define PRIME_  1000003u
#define NTOK    (B_ * S_)

// flag: 1 if token buffer is int64 (odd 32-bit words all zero), 0 if int32
__device__ int g_tok_is_64;

__global__ void detect_dtype_kernel(const unsigned* __restrict__ tok32)
{
    if (threadIdx.x == 0 && blockIdx.x == 0) {
        // Sample odd 32-bit words spread across the whole buffer.
        // int64 tokens < 2^31  => every odd word is 0.
        // int32 tokens ~U[0,50257) => P(sampled word == 0) = 1/50257 each.
        int is64 = 1;
        #pragma unroll 1
        for (int i = 0; i < 64; i++) {
            const int idx = (i * (NTOK / 64)) + 1;   // odd-ish spread; see below
            // ensure we read an ODD word index within [0, 2*NTOK)
            const int odd = (idx | 1);
            if (tok32[(odd < 2 * NTOK - 1 ? odd : 1)] != 0u) { is64 = 0; break; }
        }
        g_tok_is_64 = is64;
    }
}

__global__ __launch_bounds__(256) void engram_kernel(
    const unsigned* __restrict__ tok32,
    const float4* __restrict__ tables,
    float4* __restrict__ out)
{
    // one warp per (b, s, oi, head) output row of 256 floats
    const int gw   = (blockIdx.x * blockDim.x + threadIdx.x) >> 5;
    const int lane = threadIdx.x & 31;

    const int oh = gw & 7;        // oi*4 + head
    const int bs = gw >> 3;       // b*S + s
    const int s  = bs & (S_ - 1);
    const int b  = bs >> 12;
    const int oi   = oh >> 2;
    const int head = oh & 3;
    const int order = 2 + oi;

    const unsigned seed = 1337u + 97u * (unsigned)order + 17u * (unsigned)head;
    const int is64 = g_tok_is_64;

    // hash over the n-gram window ending at s (oldest first), zero-padded
    unsigned h = 0;
    #pragma unroll
    for (int i = 0; i < 3; i++) {
        if (i < order) {
            const int pos = s - (order - 1) + i;
            unsigned t = 0u;
            if (pos >= 0) {
                const int idx = b * S_ + pos;
                t = is64 ? tok32[2 * idx] : tok32[idx];  // little-endian low word
            }
            h = (h * PRIME_ + t + seed) & (NBUCK - 1u);
        }
    }

    // gather 256 floats (64 float4) from the table row; coalesced copy
    const float4* src = tables + ((size_t)(oi * NHEADS + head) * NBUCK + h) * (HD / 4);
    float4* dst = out + (size_t)bs * 512 + (size_t)oh * (HD / 4);

    dst[lane]      = src[lane];
    dst[lane + 32] = src[lane + 32];
}

extern "C" void kernel_launch(void* const* d_in, const int* in_sizes, int n_in,
                              void* d_out, int out_size)
{
    // Assign inputs by element count, robust to metadata ordering:
    // tokens: 4*4096 = 16384 elements; tables: 8*2048*256 = 4194304 elements.
    const void* tokens_p = d_in[0];
    const void* tables_p = d_in[1];
    if (n_in >= 2 && in_sizes[0] > in_sizes[1]) {
        tokens_p = d_in[1];
        tables_p = d_in[0];
    }

    const unsigned* tok32  = (const unsigned*)tokens_p;
    const float4*   tables = (const float4*)tables_p;
    float4*         out    = (float4*)d_out;

    detect_dtype_kernel<<<1, 32>>>(tok32);

    // total warps = B*S * 8 = 131072 ; 8 warps/block -> 16384 blocks
    const int total_warps = B_ * S_ * 8;
    const int threads = 256;
    const int blocks  = (total_warps * 32) / threads;

    engram_kernel<<<blocks, threads>>>(tok32, tables, out);
}

// round 4
// speedup vs baseline: 1.2205x; 1.2205x over previous
#include <cuda_runtime.h>
#include <cstdint>

// EngramMemory: hashed n-gram embedding gather.
// tokens: (4, 4096) int64 or int32 (dtype auto-detected in-kernel)
// tables: (8, 2048, 256) f32   (orders {2,3} x 4 heads)
// out:    (4, 4096, 2048) f32
//
// For order index oi (order = 2+oi), head hd:
//   seed = 1337 + 97*order + 17*hd
//   hash = 0; for tok in window (oldest->newest, zero-padded):
//       hash = (hash*1000003 + tok + seed) mod 2048
//   out[b,s, oi*1024 + hd*256 : +256] = tables[oi*4+hd][hash]
//
// mod 2048 is a power of two => exact in uint32:
// h <= 2047, 2047*1000003 + 50256 + seed < 2^31.

#define B_      4
#define S_      4096
#define NBUCK   2048u
#define PRIME_  1000003u
#define NTOK    (B_ * S_)

__global__ __launch_bounds__(256) void engram_kernel(
    const unsigned* __restrict__ tok32,
    const float4* __restrict__ tables,
    float4* __restrict__ out)
{
    // one warp per (b, s): copies all 8 rows of 256 floats (16 float4/lane in flight)
    const int bs   = (blockIdx.x * blockDim.x + threadIdx.x) >> 5;
    const int lane = threadIdx.x & 31;
    const int s  = bs & (S_ - 1);
    const int b  = bs >> 12;

    // ---- in-warp dtype detection ----
    // Read 8 fixed odd 32-bit words spread across the buffer (same addresses
    // chip-wide -> broadcast L2 hits). int64 tokens < 2^31 => all odd words 0.
    // int32 tokens: P(all 8 sampled words == 0) = (1/50257)^8 ~ 0.
    unsigned probe = 0u;
    if (lane < 8) probe = tok32[(lane * (2 * NTOK / 8)) | 1];
    const bool is64 = __all_sync(0xFFFFFFFFu, probe == 0u);

    // ---- load the 3-token window (zero-padded) ----
    unsigned t0 = 0u, t1 = 0u, t2;
    {
        const int base = b * S_ + s;
        if (is64) {
            t2 = tok32[2 * base];
            if (s >= 1) t1 = tok32[2 * (base - 1)];
            if (s >= 2) t0 = tok32[2 * (base - 2)];
        } else {
            t2 = tok32[base];
            if (s >= 1) t1 = tok32[base - 1];
            if (s >= 2) t0 = tok32[base - 2];
        }
    }

    // ---- 8 hashes: oi in {0,1}, head in {0..3} ----
    unsigned hash[8];
    #pragma unroll
    for (int head = 0; head < 4; head++) {
        // order 2: seed = 1337 + 97*2 + 17*head
        {
            const unsigned seed = 1337u + 194u + 17u * (unsigned)head;
            unsigned h = (t1 + seed) & (NBUCK - 1u);
            h = (h * PRIME_ + t2 + seed) & (NBUCK - 1u);
            hash[head] = h;
        }
        // order 3: seed = 1337 + 97*3 + 17*head
        {
            const unsigned seed = 1337u + 291u + 17u * (unsigned)head;
            unsigned h = (t0 + seed) & (NBUCK - 1u);
            h = (h * PRIME_ + t1 + seed) & (NBUCK - 1u);
            h = (h * PRIME_ + t2 + seed) & (NBUCK - 1u);
            hash[4 + head] = h;
        }
    }

    // ---- gather 8 rows x 512B; fully unrolled so ptxas front-batches 16 loads ----
    float4 v[16];
    #pragma unroll
    for (int oh = 0; oh < 8; oh++) {
        // table index: tables[oi*4 + head]; oh = head (oi=0) for oh<4, else 4+head (oi=1)
        const float4* src = tables + ((size_t)oh * NBUCK + hash[oh]) * 64;
        v[2 * oh]     = src[lane];
        v[2 * oh + 1] = src[lane + 32];
    }

    float4* dst = out + (size_t)bs * 512;
    #pragma unroll
    for (int oh = 0; oh < 8; oh++) {
        __stcs(dst + oh * 64 + lane,      v[2 * oh]);
        __stcs(dst + oh * 64 + lane + 32, v[2 * oh + 1]);
    }
}

extern "C" void kernel_launch(void* const* d_in, const int* in_sizes, int n_in,
                              void* d_out, int out_size)
{
    // Assign inputs by element count, robust to metadata ordering:
    // tokens: 16384 elements; tables: 4194304 elements.
    const void* tokens_p = d_in[0];
    const void* tables_p = d_in[1];
    if (n_in >= 2 && in_sizes[0] > in_sizes[1]) {
        tokens_p = d_in[1];
        tables_p = d_in[0];
    }

    const unsigned* tok32  = (const unsigned*)tokens_p;
    const float4*   tables = (const float4*)tables_p;
    float4*         out    = (float4*)d_out;

    // one warp per (b,s): 16384 warps; 8 warps/block -> 2048 blocks
    engram_kernel<<<(NTOK * 32) / 256, 256>>>(tok32, tables, out);
}